// round 16
// baseline (speedup 1.0000x reference)
#include <cuda_runtime.h>
#include <cuda_fp16.h>
#include <math.h>
#include <stdint.h>

// Problem constants: B=16, C=512, H=W=32, GROUPS=32
#define BB   16
#define CC   512
#define NN_  1024
#define CG   16
#define SCALE 0.044194173824159216f   // 512^-0.5

// ---------------------------------------------------------------------------
// Scratch (device globals)
// ---------------------------------------------------------------------------
__device__ __align__(128) __half g_xn [(size_t)BB * NN_ * CC];   // xn_t [b][n][c]
__device__ __align__(128) __half g_wv [(size_t)CC * CC];         // Wv fp16
__device__ __align__(128) __half g_wp [(size_t)CC * CC];         // w_proj fp16
__device__ __align__(128) __half g_wqT[(size_t)CC * CC];         // Wq^T fp16 [c][o]
__device__ __align__(128) __half g_wkT[(size_t)CC * CC];         // Wk^T fp16 [c][o]
__device__ __align__(128) __half g_G  [(size_t)CC * CC];         // G = Wq^T Wk  [c][c']
__device__ __align__(128) __half g_z  [(size_t)BB * NN_ * CC];   // z_t [b][n][c]
__device__ __align__(128) __half g_v  [(size_t)BB * CC * NN_];   // v [b][c][n]
__device__ __align__(128) __half g_s  [(size_t)BB * NN_ * NN_];  // scaled scores fp16
__device__ __align__(128) __half g_a  [(size_t)BB * NN_ * NN_];  // attn fp16
__device__ __align__(128) __half g_av [(size_t)BB * NN_ * CC];   // av_t [b][n][c]
__device__ __align__(128) float  g_alpha[(size_t)BB * NN_];      // xn . (Wq^T bk)
__device__ __align__(128) float  g_beta [(size_t)BB * NN_];      // xn . (Wk^T bq)
__device__ __align__(128) float  g_wqbk[CC], g_wkbq[CC];
__device__ float g_kappa[1];

// ---------------------------------------------------------------------------
// Helpers (base-target sm_80+ only)
// ---------------------------------------------------------------------------
__device__ __forceinline__ uint32_t smem_u32(const void* p) {
    uint32_t a;
    asm("{ .reg .u64 t; cvta.to.shared.u64 t, %1; cvt.u32.u64 %0, t; }" : "=r"(a) : "l"(p));
    return a;
}
__device__ __forceinline__ void ldsm4(uint32_t (&r)[4], uint32_t addr) {
    asm volatile("ldmatrix.sync.aligned.m8n8.x4.shared.b16 {%0,%1,%2,%3}, [%4];"
        : "=r"(r[0]), "=r"(r[1]), "=r"(r[2]), "=r"(r[3]) : "r"(addr));
}
__device__ __forceinline__ void mma16816(float (&c)[4], const uint32_t (&a)[4],
                                         const uint32_t b0, const uint32_t b1) {
    asm volatile("mma.sync.aligned.m16n8k16.row.col.f32.f16.f16.f32 "
        "{%0,%1,%2,%3}, {%4,%5,%6,%7}, {%8,%9}, {%0,%1,%2,%3};"
        : "+f"(c[0]), "+f"(c[1]), "+f"(c[2]), "+f"(c[3])
        : "r"(a[0]), "r"(a[1]), "r"(a[2]), "r"(a[3]), "r"(b0), "r"(b1));
}
__device__ __forceinline__ void cp16(uint32_t dst, const void* src) {
    asm volatile("cp.async.cg.shared.global [%0], [%1], 16;" :: "r"(dst), "l"(src));
}
__device__ __forceinline__ void cp_commit() {
    asm volatile("cp.async.commit_group;" ::: "memory");
}
template<int N> __device__ __forceinline__ void cp_wait() {
    asm volatile("cp.async.wait_group %0;" :: "n"(N) : "memory");
}

// ---------------------------------------------------------------------------
// fp32 -> fp16 convert
// ---------------------------------------------------------------------------
__global__ void cvt_kernel(const float* __restrict__ src, __half* __restrict__ dst, int n) {
    int i = blockIdx.x * blockDim.x + threadIdx.x;
    if (i < n) dst[i] = __float2half_rn(src[i]);
}

// ---------------------------------------------------------------------------
// Transpose + convert: src fp32 [512][512] (o,c) -> dst fp16 [c][o]
// ---------------------------------------------------------------------------
__global__ void transpose_cvt(const float* __restrict__ src, __half* __restrict__ dst) {
    __shared__ float t[32][33];
    const int bx = blockIdx.x * 32;   // c tile
    const int by = blockIdx.y * 32;   // o tile
    const int tx = threadIdx.x & 31, ty = threadIdx.x >> 5;
    #pragma unroll
    for (int r = ty; r < 32; r += 8)
        t[r][tx] = src[(size_t)(by + r) * CC + bx + tx];
    __syncthreads();
    #pragma unroll
    for (int r = ty; r < 32; r += 8)
        dst[(size_t)(bx + r) * CC + by + tx] = __float2half_rn(t[tx][r]);
}

// ---------------------------------------------------------------------------
// Bias prep: wqbk[c] = sum_o Wq[o][c]*bk[o]; wkbq[c] = sum_o Wk[o][c]*bq[o];
// kappa = bq . bk    (zero for this problem's inputs; kept for exactness)
// ---------------------------------------------------------------------------
__global__ void biasprep_kernel(const float* __restrict__ w_qkv,
                                const float* __restrict__ b_qkv) {
    const int c = blockIdx.x * 128 + threadIdx.x;
    if (threadIdx.x < 128 && c < CC) {
        float s1 = 0.f, s2 = 0.f;
        #pragma unroll 4
        for (int o = 0; o < CC; o++) {
            s1 += w_qkv[(size_t)o * CC + c]        * b_qkv[CC + o];  // Wq^T bk
            s2 += w_qkv[(size_t)(CC + o) * CC + c] * b_qkv[o];       // Wk^T bq
        }
        g_wqbk[c] = s1; g_wkbq[c] = s2;
    }
    if (blockIdx.x == 0 && threadIdx.x == 128) {
        float k = 0.f;
        for (int o = 0; o < CC; o++) k += b_qkv[o] * b_qkv[CC + o];
        g_kappa[0] = k;
    }
}

// ---------------------------------------------------------------------------
// alpha[n] = xn_t[n] . wqbk ; beta[n] = xn_t[n] . wkbq   (one warp per row)
// ---------------------------------------------------------------------------
__global__ void alphabeta_kernel(const __half* __restrict__ xn,
                                 float* __restrict__ alpha, float* __restrict__ beta) {
    const int n = blockIdx.x * 8 + (threadIdx.x >> 5);
    const int lane = threadIdx.x & 31;
    const __half* row = xn + (size_t)n * CC;
    float a = 0.f, b2 = 0.f;
    for (int c = lane; c < CC; c += 32) {
        float xv = __half2float(row[c]);
        a  += xv * g_wqbk[c];
        b2 += xv * g_wkbq[c];
    }
    #pragma unroll
    for (int o = 16; o; o >>= 1) {
        a  += __shfl_down_sync(0xffffffffu, a,  o);
        b2 += __shfl_down_sync(0xffffffffu, b2, o);
    }
    if (lane == 0) { alpha[n] = a; beta[n] = b2; }
}

// ---------------------------------------------------------------------------
// GroupNorm -> transposed fp16 output xn_t[b][n][c]
// ---------------------------------------------------------------------------
__global__ void gn_kernel(const float* __restrict__ x,
                          const float* __restrict__ gamma,
                          const float* __restrict__ beta) {
    extern __shared__ float xs[];
    const int b = blockIdx.x >> 5;
    const int g = blockIdx.x & 31;
    const size_t base = ((size_t)b * CC + (size_t)g * CG) * NN_;
    const float4* __restrict__ x4 = (const float4*)(x + base);

    float s = 0.f, s2 = 0.f;
    for (int i = threadIdx.x; i < CG * NN_ / 4; i += 256) {
        float4 v = x4[i];
        ((float4*)xs)[i] = v;
        s  += v.x + v.y + v.z + v.w;
        s2 += v.x * v.x + v.y * v.y + v.z * v.z + v.w * v.w;
    }
    #pragma unroll
    for (int o = 16; o; o >>= 1) {
        s  += __shfl_down_sync(0xffffffffu, s,  o);
        s2 += __shfl_down_sync(0xffffffffu, s2, o);
    }
    __shared__ float2 sh[8];
    __shared__ float sga[16], sbe[16];
    if ((threadIdx.x & 31) == 0) sh[threadIdx.x >> 5] = make_float2(s, s2);
    __syncthreads();
    if (threadIdx.x < 16) {
        float ts = 0.f, ts2 = 0.f;
        #pragma unroll
        for (int i = 0; i < 8; i++) { ts += sh[i].x; ts2 += sh[i].y; }
        const float inv = 1.f / (float)(CG * NN_);
        float mu  = ts * inv;
        float var = ts2 * inv - mu * mu;
        float rstd = rsqrtf(var + 1e-5f);
        int c = g * CG + threadIdx.x;
        float ga = gamma[c] * rstd;
        sga[threadIdx.x] = ga;
        sbe[threadIdx.x] = beta[c] - mu * ga;
    }
    __syncthreads();

    for (int n = threadIdx.x; n < NN_; n += 256) {
        __align__(16) __half hh[16];
        #pragma unroll
        for (int c = 0; c < 16; c++)
            hh[c] = __float2half_rn(xs[c * NN_ + n] * sga[c] + sbe[c]);
        size_t o = ((size_t)(b * NN_ + n)) * CC + g * CG;
        *(uint4*)(g_xn + o)     = *(uint4*)(hh);
        *(uint4*)(g_xn + o + 8) = *(uint4*)(hh + 8);
    }
}

// ---------------------------------------------------------------------------
// fp16 HMMA GEMM:  D[M,N] = sum_k A[m][k] * B[n][k]   (both K-major)
// 128x128 CTA tile, BK=64, 8 warps (64x32), 3-stage cp.async ring, 2 CTA/SM.
// Register-level fragment double-buffering across k16 steps.
// EPI: 1=fp16+row bias, 3=fp16, 4=fp32+row bias+resid,
//      5=fp16 scores: (acc+alpha_i+beta_j+kappa)*SCALE
// ---------------------------------------------------------------------------
#define STAGE_BYTES 32768              // A 16KB + B 16KB
#define NSTAGE      3
#define SMEM_BYTES  (NSTAGE * STAGE_BYTES)

template<int EPI>
__global__ void __launch_bounds__(256, 2) gemm_hh(
    const __half* __restrict__ A, size_t aBatch, int ldA,
    const __half* __restrict__ B, size_t bBatch, int ldB,
    int K,
    __half* __restrict__ outH, float* __restrict__ outF,
    size_t oBatch, int ldO,
    const float* __restrict__ bias, const float* __restrict__ resid)
{
    extern __shared__ char smem[];
    const uint32_t sb = smem_u32(smem);

    const int tid = threadIdx.x, lane = tid & 31, wid = tid >> 5;
    const int wm = wid >> 2, wn = wid & 3;
    const int b  = blockIdx.z;
    const int m0 = blockIdx.y * 128, n0 = blockIdx.x * 128;

    const __half* srcA = A + (size_t)b * aBatch + (size_t)m0 * ldA;
    const __half* srcB = B + (size_t)b * bBatch + (size_t)n0 * ldB;

    float acc[4][4][4];
    #pragma unroll
    for (int i = 0; i < 4; i++)
        #pragma unroll
        for (int j = 0; j < 4; j++)
            #pragma unroll
            for (int q = 0; q < 4; q++) acc[i][j][q] = 0.f;

    const int T = K / 64;

    const int l_row = tid >> 1;
    const int l_g0  = (tid & 1) * 4;
    auto load_stage = [&](int t) {
        const int k0 = t * 64;
        const uint32_t sbuf = sb + (uint32_t)(t % NSTAGE) * STAGE_BYTES;
        const uint32_t rowOff = (uint32_t)l_row * 128;
        #pragma unroll
        for (int q = 0; q < 4; q++) {
            const int g = l_g0 + q;
            const uint32_t sw = (uint32_t)((g ^ (l_row & 7)) << 4);
            cp16(sbuf + rowOff + sw,          srcA + (size_t)l_row * ldA + k0 + g * 8);
            cp16(sbuf + 16384 + rowOff + sw,  srcB + (size_t)l_row * ldB + k0 + g * 8);
        }
    };

    const int arow = lane & 15;
    const int akhi = lane >> 4;
    const int brow = ((lane >> 4) << 3) | (lane & 7);
    const int bkhi = (lane >> 3) & 1;
    const uint32_t aRowOff = (uint32_t)(wm * 64 + arow) * 128;
    const uint32_t bRowOff = (uint32_t)(wn * 32 + brow) * 128 + 16384u;
    const uint32_t l7 = (uint32_t)(lane & 7);

    uint32_t af[2][4][4], bf[2][2][4];

    auto ld_frags = [&](uint32_t sbuf, int k16, int buf) {
        const uint32_t aSw = (uint32_t)(((k16 * 2 + akhi) ^ l7) << 4);
        const uint32_t bSw = (uint32_t)(((k16 * 2 + bkhi) ^ l7) << 4);
        #pragma unroll
        for (int i = 0; i < 4; i++)
            ldsm4(af[buf][i], sbuf + aRowOff + (uint32_t)(i * 16 * 128) + aSw);
        #pragma unroll
        for (int j = 0; j < 2; j++)
            ldsm4(bf[buf][j], sbuf + bRowOff + (uint32_t)(j * 16 * 128) + bSw);
    };

    load_stage(0); cp_commit();
    load_stage(1); cp_commit();

    for (int t = 0; t < T; t++) {
        cp_wait<1>();
        __syncthreads();

        const uint32_t sbuf = sb + (uint32_t)(t % NSTAGE) * STAGE_BYTES;
        ld_frags(sbuf, 0, 0);

        if (t + 2 < T) load_stage(t + 2);
        cp_commit();

        #pragma unroll
        for (int k16 = 0; k16 < 4; k16++) {
            const int cur = k16 & 1;
            if (k16 < 3) ld_frags(sbuf, k16 + 1, cur ^ 1);
            #pragma unroll
            for (int i = 0; i < 4; i++)
                #pragma unroll
                for (int j = 0; j < 2; j++) {
                    mma16816(acc[i][2 * j],     af[cur][i], bf[cur][j][0], bf[cur][j][1]);
                    mma16816(acc[i][2 * j + 1], af[cur][i], bf[cur][j][2], bf[cur][j][3]);
                }
        }
    }

    // epilogue
    const int rbase = m0 + wm * 64 + (lane >> 2);
    const int cbase = n0 + wn * 32 + (lane & 3) * 2;

    float kap = 0.f;
    if (EPI == 5) kap = outF[0];

    float bc0[4], bc1[4];
    if (EPI == 5) {
        #pragma unroll
        for (int j = 0; j < 4; j++) {
            bc0[j] = resid[(size_t)b * NN_ + cbase + j * 8];
            bc1[j] = resid[(size_t)b * NN_ + cbase + j * 8 + 1];
        }
    }

    #pragma unroll
    for (int i = 0; i < 4; i++) {
        const int row0 = rbase + i * 16, row1 = row0 + 8;
        float br0 = 0.f, br1 = 0.f;
        if (EPI == 1 || EPI == 4) { br0 = bias[row0]; br1 = bias[row1]; }
        if (EPI == 5) {
            br0 = bias[(size_t)b * NN_ + row0] + kap;
            br1 = bias[(size_t)b * NN_ + row1] + kap;
        }
        #pragma unroll
        for (int j = 0; j < 4; j++) {
            const int col = cbase + j * 8;
            const size_t ob0 = (size_t)b * oBatch + (size_t)row0 * ldO + col;
            const size_t ob1 = (size_t)b * oBatch + (size_t)row1 * ldO + col;
            float v0 = acc[i][j][0], v1 = acc[i][j][1];
            float v2 = acc[i][j][2], v3 = acc[i][j][3];
            if (EPI == 5) {
                *(__half2*)(outH + ob0) = __floats2half2_rn((v0 + br0 + bc0[j]) * SCALE,
                                                            (v1 + br0 + bc1[j]) * SCALE);
                *(__half2*)(outH + ob1) = __floats2half2_rn((v2 + br1 + bc0[j]) * SCALE,
                                                            (v3 + br1 + bc1[j]) * SCALE);
            } else if (EPI == 4) {
                float2 r0 = *(const float2*)(resid + ob0);
                float2 r1 = *(const float2*)(resid + ob1);
                *(float2*)(outF + ob0) = make_float2(v0 + br0 + r0.x, v1 + br0 + r0.y);
                *(float2*)(outF + ob1) = make_float2(v2 + br1 + r1.x, v3 + br1 + r1.y);
            } else {
                if (EPI == 1) { v0 += br0; v1 += br0; v2 += br1; v3 += br1; }
                *(__half2*)(outH + ob0) = __floats2half2_rn(v0, v1);
                *(__half2*)(outH + ob1) = __floats2half2_rn(v2, v3);
            }
        }
    }
}

// ---------------------------------------------------------------------------
// Softmax over rows of fp16 scores -> fp16 attn.
// ---------------------------------------------------------------------------
__global__ void softmax_kernel(const __half* __restrict__ src, __half* __restrict__ dst) {
    const size_t rbase = (size_t)blockIdx.x * NN_;
    uint2 rv = *(const uint2*)(src + rbase + threadIdx.x * 4);
    float2 a0 = __half22float2(*(const __half2*)&rv.x);
    float2 a1 = __half22float2(*(const __half2*)&rv.y);

    float m = fmaxf(fmaxf(a0.x, a0.y), fmaxf(a1.x, a1.y));
    #pragma unroll
    for (int o = 16; o; o >>= 1) m = fmaxf(m, __shfl_xor_sync(0xffffffffu, m, o));
    __shared__ float shm[8], shs[8];
    if ((threadIdx.x & 31) == 0) shm[threadIdx.x >> 5] = m;
    __syncthreads();
    float M = shm[0];
    #pragma unroll
    for (int i = 1; i < 8; i++) M = fmaxf(M, shm[i]);

    a0.x = __expf(a0.x - M); a0.y = __expf(a0.y - M);
    a1.x = __expf(a1.x - M); a1.y = __expf(a1.y - M);
    float s = a0.x + a0.y + a1.x + a1.y;
    #pragma unroll
    for (int o = 16; o; o >>= 1) s += __shfl_xor_sync(0xffffffffu, s, o);
    if ((threadIdx.x & 31) == 0) shs[threadIdx.x >> 5] = s;
    __syncthreads();
    float S = 0.f;
    #pragma unroll
    for (int i = 0; i < 8; i++) S += shs[i];
    const float r = 1.f / S;

    __half2 h0 = __floats2half2_rn(a0.x * r, a0.y * r);
    __half2 h1 = __floats2half2_rn(a1.x * r, a1.y * r);
    uint2 wv;
    wv.x = *(const uint32_t*)&h0;
    wv.y = *(const uint32_t*)&h1;
    *(uint2*)(dst + rbase + threadIdx.x * 4) = wv;
}

// ---------------------------------------------------------------------------
// Launch — 3 streams / 5 events. sV: [transposes -> G -> biasprep] = evPre
// (hidden under GN), then cvt(Wv)+cvt(Wp) -> V = evV. Chains: alphabeta ->
// z=xn.G -> scores -> softmax -> AV -> proj.
// ---------------------------------------------------------------------------
static cudaStream_t sB = nullptr, sV = nullptr;
static cudaEvent_t evFork = nullptr, evGN = nullptr, evPre = nullptr,
                   evV = nullptr, evP1 = nullptr;

extern "C" void kernel_launch(void* const* d_in, const int* in_sizes, int n_in,
                              void* d_out, int out_size) {
    const float* x      = (const float*)d_in[0];
    const float* gamma  = (const float*)d_in[1];
    const float* beta   = (const float*)d_in[2];
    const float* w_qkv  = (const float*)d_in[3];
    const float* b_qkv  = (const float*)d_in[4];
    const float* w_proj = (const float*)d_in[5];
    const float* b_proj = (const float*)d_in[6];
    float* y = (float*)d_out;

    if (!sB) {
        cudaStreamCreateWithFlags(&sB, cudaStreamNonBlocking);
        cudaStreamCreateWithFlags(&sV, cudaStreamNonBlocking);
        cudaEventCreateWithFlags(&evFork, cudaEventDisableTiming);
        cudaEventCreateWithFlags(&evGN,   cudaEventDisableTiming);
        cudaEventCreateWithFlags(&evPre,  cudaEventDisableTiming);
        cudaEventCreateWithFlags(&evV,    cudaEventDisableTiming);
        cudaEventCreateWithFlags(&evP1,   cudaEventDisableTiming);
    }

    cudaFuncSetAttribute(gn_kernel,  cudaFuncAttributeMaxDynamicSharedMemorySize, 65536);
    cudaFuncSetAttribute(gemm_hh<1>, cudaFuncAttributeMaxDynamicSharedMemorySize, SMEM_BYTES);
    cudaFuncSetAttribute(gemm_hh<3>, cudaFuncAttributeMaxDynamicSharedMemorySize, SMEM_BYTES);
    cudaFuncSetAttribute(gemm_hh<4>, cudaFuncAttributeMaxDynamicSharedMemorySize, SMEM_BYTES);
    cudaFuncSetAttribute(gemm_hh<5>, cudaFuncAttributeMaxDynamicSharedMemorySize, SMEM_BYTES);

    __half *xn, *wv, *wp, *wqT, *wkT, *G, *z, *v, *s16, *a, *av;
    float *alpha, *bet, *kappa;
    cudaGetSymbolAddress((void**)&xn,  g_xn);
    cudaGetSymbolAddress((void**)&wv,  g_wv);
    cudaGetSymbolAddress((void**)&wp,  g_wp);
    cudaGetSymbolAddress((void**)&wqT, g_wqT);
    cudaGetSymbolAddress((void**)&wkT, g_wkT);
    cudaGetSymbolAddress((void**)&G,   g_G);
    cudaGetSymbolAddress((void**)&z,   g_z);
    cudaGetSymbolAddress((void**)&v,   g_v);
    cudaGetSymbolAddress((void**)&s16, g_s);
    cudaGetSymbolAddress((void**)&a,   g_a);
    cudaGetSymbolAddress((void**)&av,  g_av);
    cudaGetSymbolAddress((void**)&alpha, g_alpha);
    cudaGetSymbolAddress((void**)&bet,   g_beta);
    cudaGetSymbolAddress((void**)&kappa, g_kappa);

    const int HB = BB / 2;                           // 8 batches per chain
    const size_t bQ = (size_t)NN_ * NN_;
    const size_t bX = (size_t)NN_ * CC;
    const size_t bV = (size_t)CC * NN_;

    // fork
    cudaEventRecord(evFork, 0);
    cudaStreamWaitEvent(sV, evFork, 0);
    cudaStreamWaitEvent(sB, evFork, 0);

    // sV: minimal chain-gating prologue first (hides under GN)
    transpose_cvt<<<dim3(16, 16), 256, 0, sV>>>(w_qkv, wqT);
    transpose_cvt<<<dim3(16, 16), 256, 0, sV>>>(w_qkv + (size_t)CC * CC, wkT);
    gemm_hh<3><<<dim3(4, 4, 1), 256, SMEM_BYTES, sV>>>(
        wqT, 0, CC,
        wkT, 0, CC, CC,
        G, nullptr, 0, CC, nullptr, nullptr);          // G = Wq^T Wk
    biasprep_kernel<<<4, 256, 0, sV>>>(w_qkv, b_qkv);
    cudaEventRecord(evPre, sV);

    // main: GroupNorm (all batches)
    gn_kernel<<<BB * 32, 256, 65536>>>(x, gamma, beta);
    cudaEventRecord(evGN, 0);

    // sV: converts needed only by V/proj, then V GEMM
    cvt_kernel<<<(CC * CC + 255) / 256, 256, 0, sV>>>(w_qkv + (size_t)2 * CC * CC, wv, CC * CC);
    cvt_kernel<<<(CC * CC + 255) / 256, 256, 0, sV>>>(w_proj, wp, CC * CC);
    cudaStreamWaitEvent(sV, evGN, 0);
    gemm_hh<1><<<dim3(8, 4, BB), 256, SMEM_BYTES, sV>>>(
        wv, 0, CC,
        xn, bX, CC, CC,
        v, nullptr, bV, NN_, b_qkv + 2 * CC, nullptr);
    cudaEventRecord(evV, sV);

    // ---- two chains (8 batches each), interleaved stage-by-stage ----
    cudaStreamWaitEvent(0, evPre, 0);
    cudaStreamWaitEvent(sB, evPre, 0);
    cudaStreamWaitEvent(sB, evGN, 0);

    cudaStream_t st[2] = { 0, sB };
    __half* z_h[2]; __half* s_h[2]; __half* a_h[2]; __half* xn_h[2];
    __half* v_h[2]; __half* av_h[2]; float* y_h[2]; const float* x_h[2];
    float* al_h[2]; float* be_h[2];
    for (int h = 0; h < 2; h++) {
        const int bo = h * HB;
        z_h[h]   = z   + (size_t)bo * bX;
        s_h[h]   = s16 + (size_t)bo * bQ;
        a_h[h]   = a   + (size_t)bo * bQ;
        xn_h[h]  = xn  + (size_t)bo * bX;
        v_h[h]   = v   + (size_t)bo * bV;
        av_h[h]  = av  + (size_t)bo * bX;
        y_h[h]   = y   + (size_t)bo * bV;
        x_h[h]   = x   + (size_t)bo * bV;
        al_h[h]  = alpha + (size_t)bo * NN_;
        be_h[h]  = bet   + (size_t)bo * NN_;
    }

    // alpha/beta (cheap exact bias corrections)
    for (int h = 0; h < 2; h++)
        alphabeta_kernel<<<HB * NN_ / 8, 256, 0, st[h]>>>(xn_h[h], al_h[h], be_h[h]);

    // z = xn . G  (replaces both q and k projections)
    for (int h = 0; h < 2; h++)
        gemm_hh<3><<<dim3(4, 8, HB), 256, SMEM_BYTES, st[h]>>>(
            xn_h[h], bX, CC,
            G, 0, CC, CC,
            z_h[h], nullptr, bX, CC, nullptr, nullptr);

    // scores: S[i][j] = (xn_i . z_j + alpha_i + beta_j + kappa) * SCALE
    for (int h = 0; h < 2; h++)
        gemm_hh<5><<<dim3(8, 8, HB), 256, SMEM_BYTES, st[h]>>>(
            xn_h[h], bX, CC,
            z_h[h], bX, CC, CC,
            s_h[h], kappa, bQ, NN_, al_h[h], be_h[h]);

    // softmax
    for (int h = 0; h < 2; h++)
        softmax_kernel<<<HB * NN_, 256, 0, st[h]>>>(s_h[h], a_h[h]);

    // AV
    for (int h = 0; h < 2; h++) {
        cudaStreamWaitEvent(st[h], evV, 0);
        gemm_hh<3><<<dim3(4, 8, HB), 256, SMEM_BYTES, st[h]>>>(
            a_h[h], bQ, NN_,
            v_h[h], bV, NN_, NN_,
            av_h[h], nullptr, bX, CC, nullptr, nullptr);
    }

    // proj + residual
    for (int h = 0; h < 2; h++)
        gemm_hh<4><<<dim3(8, 4, HB), 256, SMEM_BYTES, st[h]>>>(
            wp, 0, CC,
            av_h[h], bX, CC, CC,
            nullptr, y_h[h], bV, NN_, b_proj, x_h[h]);

    // join sB back into stream 0
    cudaEventRecord(evP1, sB);
    cudaStreamWaitEvent(0, evP1, 0);
}

// round 17
// speedup vs baseline: 1.1666x; 1.1666x over previous
#include <cuda_runtime.h>
#include <cuda_fp16.h>
#include <math.h>
#include <stdint.h>

// Problem constants: B=16, C=512, H=W=32, GROUPS=32
#define BB   16
#define CC   512
#define NN_  1024
#define CG   16
#define SCALE 0.044194173824159216f   // 512^-0.5

// ---------------------------------------------------------------------------
// Scratch (device globals)
// ---------------------------------------------------------------------------
__device__ __align__(128) __half g_xn [(size_t)BB * NN_ * CC];   // xn_t [b][n][c]
__device__ __align__(128) __half g_wv [(size_t)CC * CC];         // Wv fp16
__device__ __align__(128) __half g_wp [(size_t)CC * CC];         // w_proj fp16
__device__ __align__(128) __half g_wqT[(size_t)CC * CC];         // Wq^T fp16 [c][o]
__device__ __align__(128) __half g_wkT[(size_t)CC * CC];         // Wk^T fp16 [c][o]
__device__ __align__(128) __half g_G  [(size_t)CC * CC];         // G = Wq^T Wk  [c][c']
__device__ __align__(128) __half g_z  [(size_t)BB * NN_ * CC];   // z_t [b][n][c]
__device__ __align__(128) __half g_v  [(size_t)BB * CC * NN_];   // v [b][c][n]
__device__ __align__(128) __half g_s  [(size_t)BB * NN_ * NN_];  // scaled scores fp16
__device__ __align__(128) __half g_a  [(size_t)BB * NN_ * NN_];  // attn fp16
__device__ __align__(128) __half g_av [(size_t)BB * NN_ * CC];   // av_t [b][n][c]
__device__ __align__(128) float  g_betaN[(size_t)BB * NN_];      // beta_j = xn_j . (Wk^T bq)
__device__ __align__(128) float  g_wkbq[CC];

// ---------------------------------------------------------------------------
// Helpers (base-target sm_80+ only)
// ---------------------------------------------------------------------------
__device__ __forceinline__ uint32_t smem_u32(const void* p) {
    uint32_t a;
    asm("{ .reg .u64 t; cvta.to.shared.u64 t, %1; cvt.u32.u64 %0, t; }" : "=r"(a) : "l"(p));
    return a;
}
__device__ __forceinline__ void ldsm4(uint32_t (&r)[4], uint32_t addr) {
    asm volatile("ldmatrix.sync.aligned.m8n8.x4.shared.b16 {%0,%1,%2,%3}, [%4];"
        : "=r"(r[0]), "=r"(r[1]), "=r"(r[2]), "=r"(r[3]) : "r"(addr));
}
__device__ __forceinline__ void mma16816(float (&c)[4], const uint32_t (&a)[4],
                                         const uint32_t b0, const uint32_t b1) {
    asm volatile("mma.sync.aligned.m16n8k16.row.col.f32.f16.f16.f32 "
        "{%0,%1,%2,%3}, {%4,%5,%6,%7}, {%8,%9}, {%0,%1,%2,%3};"
        : "+f"(c[0]), "+f"(c[1]), "+f"(c[2]), "+f"(c[3])
        : "r"(a[0]), "r"(a[1]), "r"(a[2]), "r"(a[3]), "r"(b0), "r"(b1));
}
__device__ __forceinline__ void cp16(uint32_t dst, const void* src) {
    asm volatile("cp.async.cg.shared.global [%0], [%1], 16;" :: "r"(dst), "l"(src));
}
__device__ __forceinline__ void cp_commit() {
    asm volatile("cp.async.commit_group;" ::: "memory");
}
template<int N> __device__ __forceinline__ void cp_wait() {
    asm volatile("cp.async.wait_group %0;" :: "n"(N) : "memory");
}

// ---------------------------------------------------------------------------
// fp32 -> fp16 convert
// ---------------------------------------------------------------------------
__global__ void cvt_kernel(const float* __restrict__ src, __half* __restrict__ dst, int n) {
    int i = blockIdx.x * blockDim.x + threadIdx.x;
    if (i < n) dst[i] = __float2half_rn(src[i]);
}

// ---------------------------------------------------------------------------
// Transpose + convert: src fp32 [512][512] (o,c) -> dst fp16 [c][o]
// ---------------------------------------------------------------------------
__global__ void transpose_cvt(const float* __restrict__ src, __half* __restrict__ dst) {
    __shared__ float t[32][33];
    const int bx = blockIdx.x * 32;   // c tile
    const int by = blockIdx.y * 32;   // o tile
    const int tx = threadIdx.x & 31, ty = threadIdx.x >> 5;
    #pragma unroll
    for (int r = ty; r < 32; r += 8)
        t[r][tx] = src[(size_t)(by + r) * CC + bx + tx];
    __syncthreads();
    #pragma unroll
    for (int r = ty; r < 32; r += 8)
        dst[(size_t)(bx + r) * CC + by + tx] = __float2half_rn(t[tx][r]);
}

// ---------------------------------------------------------------------------
// wkbq[c] = sum_o WkT[c][o] * bq[o]   — warp per c, coalesced fp16 rows.
// (alpha_i and kappa are row-constant in the softmax and cancel exactly.)
// ---------------------------------------------------------------------------
__global__ void wkbq_kernel(const __half* __restrict__ wkT,
                            const float* __restrict__ b_qkv) {
    const int c = blockIdx.x * 8 + (threadIdx.x >> 5);
    const int lane = threadIdx.x & 31;
    const __half* row = wkT + (size_t)c * CC;
    float s = 0.f;
    for (int o = lane; o < CC; o += 32)
        s += __half2float(row[o]) * b_qkv[o];
    #pragma unroll
    for (int o = 16; o; o >>= 1) s += __shfl_down_sync(0xffffffffu, s, o);
    if (lane == 0) g_wkbq[c] = s;
}

// ---------------------------------------------------------------------------
// betaN[n] = xn_t[n] . wkbq   (one warp per row)
// ---------------------------------------------------------------------------
__global__ void beta_kernel(const __half* __restrict__ xn, float* __restrict__ betaN) {
    const int n = blockIdx.x * 8 + (threadIdx.x >> 5);
    const int lane = threadIdx.x & 31;
    const __half* row = xn + (size_t)n * CC;
    float b2 = 0.f;
    for (int c = lane; c < CC; c += 32)
        b2 += __half2float(row[c]) * g_wkbq[c];
    #pragma unroll
    for (int o = 16; o; o >>= 1) b2 += __shfl_down_sync(0xffffffffu, b2, o);
    if (lane == 0) betaN[n] = b2;
}

// ---------------------------------------------------------------------------
// GroupNorm -> transposed fp16 output xn_t[b][n][c]
// ---------------------------------------------------------------------------
__global__ void gn_kernel(const float* __restrict__ x,
                          const float* __restrict__ gamma,
                          const float* __restrict__ beta) {
    extern __shared__ float xs[];
    const int b = blockIdx.x >> 5;
    const int g = blockIdx.x & 31;
    const size_t base = ((size_t)b * CC + (size_t)g * CG) * NN_;
    const float4* __restrict__ x4 = (const float4*)(x + base);

    float s = 0.f, s2 = 0.f;
    for (int i = threadIdx.x; i < CG * NN_ / 4; i += 256) {
        float4 v = x4[i];
        ((float4*)xs)[i] = v;
        s  += v.x + v.y + v.z + v.w;
        s2 += v.x * v.x + v.y * v.y + v.z * v.z + v.w * v.w;
    }
    #pragma unroll
    for (int o = 16; o; o >>= 1) {
        s  += __shfl_down_sync(0xffffffffu, s,  o);
        s2 += __shfl_down_sync(0xffffffffu, s2, o);
    }
    __shared__ float2 sh[8];
    __shared__ float sga[16], sbe[16];
    if ((threadIdx.x & 31) == 0) sh[threadIdx.x >> 5] = make_float2(s, s2);
    __syncthreads();
    if (threadIdx.x < 16) {
        float ts = 0.f, ts2 = 0.f;
        #pragma unroll
        for (int i = 0; i < 8; i++) { ts += sh[i].x; ts2 += sh[i].y; }
        const float inv = 1.f / (float)(CG * NN_);
        float mu  = ts * inv;
        float var = ts2 * inv - mu * mu;
        float rstd = rsqrtf(var + 1e-5f);
        int c = g * CG + threadIdx.x;
        float ga = gamma[c] * rstd;
        sga[threadIdx.x] = ga;
        sbe[threadIdx.x] = beta[c] - mu * ga;
    }
    __syncthreads();

    for (int n = threadIdx.x; n < NN_; n += 256) {
        __align__(16) __half hh[16];
        #pragma unroll
        for (int c = 0; c < 16; c++)
            hh[c] = __float2half_rn(xs[c * NN_ + n] * sga[c] + sbe[c]);
        size_t o = ((size_t)(b * NN_ + n)) * CC + g * CG;
        *(uint4*)(g_xn + o)     = *(uint4*)(hh);
        *(uint4*)(g_xn + o + 8) = *(uint4*)(hh + 8);
    }
}

// ---------------------------------------------------------------------------
// fp16 HMMA GEMM:  D[M,N] = sum_k A[m][k] * B[n][k]   (both K-major)
// 128x128 CTA tile, BK=64, 8 warps (64x32), 3-stage cp.async ring, 2 CTA/SM.
// Register-level fragment double-buffering across k16 steps.
// EPI: 1=fp16+row bias, 3=fp16, 4=fp32+row bias+resid,
//      5=fp16 scores: (acc + beta_j) * SCALE   (bias = per-batch beta array)
// ---------------------------------------------------------------------------
#define STAGE_BYTES 32768              // A 16KB + B 16KB
#define NSTAGE      3
#define SMEM_BYTES  (NSTAGE * STAGE_BYTES)

template<int EPI>
__global__ void __launch_bounds__(256, 2) gemm_hh(
    const __half* __restrict__ A, size_t aBatch, int ldA,
    const __half* __restrict__ B, size_t bBatch, int ldB,
    int K,
    __half* __restrict__ outH, float* __restrict__ outF,
    size_t oBatch, int ldO,
    const float* __restrict__ bias, const float* __restrict__ resid)
{
    extern __shared__ char smem[];
    const uint32_t sb = smem_u32(smem);

    const int tid = threadIdx.x, lane = tid & 31, wid = tid >> 5;
    const int wm = wid >> 2, wn = wid & 3;
    const int b  = blockIdx.z;
    const int m0 = blockIdx.y * 128, n0 = blockIdx.x * 128;

    const __half* srcA = A + (size_t)b * aBatch + (size_t)m0 * ldA;
    const __half* srcB = B + (size_t)b * bBatch + (size_t)n0 * ldB;

    float acc[4][4][4];
    #pragma unroll
    for (int i = 0; i < 4; i++)
        #pragma unroll
        for (int j = 0; j < 4; j++)
            #pragma unroll
            for (int q = 0; q < 4; q++) acc[i][j][q] = 0.f;

    const int T = K / 64;

    const int l_row = tid >> 1;
    const int l_g0  = (tid & 1) * 4;
    auto load_stage = [&](int t) {
        const int k0 = t * 64;
        const uint32_t sbuf = sb + (uint32_t)(t % NSTAGE) * STAGE_BYTES;
        const uint32_t rowOff = (uint32_t)l_row * 128;
        #pragma unroll
        for (int q = 0; q < 4; q++) {
            const int g = l_g0 + q;
            const uint32_t sw = (uint32_t)((g ^ (l_row & 7)) << 4);
            cp16(sbuf + rowOff + sw,          srcA + (size_t)l_row * ldA + k0 + g * 8);
            cp16(sbuf + 16384 + rowOff + sw,  srcB + (size_t)l_row * ldB + k0 + g * 8);
        }
    };

    const int arow = lane & 15;
    const int akhi = lane >> 4;
    const int brow = ((lane >> 4) << 3) | (lane & 7);
    const int bkhi = (lane >> 3) & 1;
    const uint32_t aRowOff = (uint32_t)(wm * 64 + arow) * 128;
    const uint32_t bRowOff = (uint32_t)(wn * 32 + brow) * 128 + 16384u;
    const uint32_t l7 = (uint32_t)(lane & 7);

    uint32_t af[2][4][4], bf[2][2][4];

    auto ld_frags = [&](uint32_t sbuf, int k16, int buf) {
        const uint32_t aSw = (uint32_t)(((k16 * 2 + akhi) ^ l7) << 4);
        const uint32_t bSw = (uint32_t)(((k16 * 2 + bkhi) ^ l7) << 4);
        #pragma unroll
        for (int i = 0; i < 4; i++)
            ldsm4(af[buf][i], sbuf + aRowOff + (uint32_t)(i * 16 * 128) + aSw);
        #pragma unroll
        for (int j = 0; j < 2; j++)
            ldsm4(bf[buf][j], sbuf + bRowOff + (uint32_t)(j * 16 * 128) + bSw);
    };

    load_stage(0); cp_commit();
    load_stage(1); cp_commit();

    for (int t = 0; t < T; t++) {
        cp_wait<1>();
        __syncthreads();

        const uint32_t sbuf = sb + (uint32_t)(t % NSTAGE) * STAGE_BYTES;
        ld_frags(sbuf, 0, 0);

        if (t + 2 < T) load_stage(t + 2);
        cp_commit();

        #pragma unroll
        for (int k16 = 0; k16 < 4; k16++) {
            const int cur = k16 & 1;
            if (k16 < 3) ld_frags(sbuf, k16 + 1, cur ^ 1);
            #pragma unroll
            for (int i = 0; i < 4; i++)
                #pragma unroll
                for (int j = 0; j < 2; j++) {
                    mma16816(acc[i][2 * j],     af[cur][i], bf[cur][j][0], bf[cur][j][1]);
                    mma16816(acc[i][2 * j + 1], af[cur][i], bf[cur][j][2], bf[cur][j][3]);
                }
        }
    }

    // epilogue
    const int rbase = m0 + wm * 64 + (lane >> 2);
    const int cbase = n0 + wn * 32 + (lane & 3) * 2;

    float bc0[4], bc1[4];
    if (EPI == 5) {
        #pragma unroll
        for (int j = 0; j < 4; j++) {
            bc0[j] = bias[(size_t)b * NN_ + cbase + j * 8];
            bc1[j] = bias[(size_t)b * NN_ + cbase + j * 8 + 1];
        }
    }

    #pragma unroll
    for (int i = 0; i < 4; i++) {
        const int row0 = rbase + i * 16, row1 = row0 + 8;
        float br0 = 0.f, br1 = 0.f;
        if (EPI == 1 || EPI == 4) { br0 = bias[row0]; br1 = bias[row1]; }
        #pragma unroll
        for (int j = 0; j < 4; j++) {
            const int col = cbase + j * 8;
            const size_t ob0 = (size_t)b * oBatch + (size_t)row0 * ldO + col;
            const size_t ob1 = (size_t)b * oBatch + (size_t)row1 * ldO + col;
            float v0 = acc[i][j][0], v1 = acc[i][j][1];
            float v2 = acc[i][j][2], v3 = acc[i][j][3];
            if (EPI == 5) {
                *(__half2*)(outH + ob0) = __floats2half2_rn((v0 + bc0[j]) * SCALE,
                                                            (v1 + bc1[j]) * SCALE);
                *(__half2*)(outH + ob1) = __floats2half2_rn((v2 + bc0[j]) * SCALE,
                                                            (v3 + bc1[j]) * SCALE);
            } else if (EPI == 4) {
                float2 r0 = *(const float2*)(resid + ob0);
                float2 r1 = *(const float2*)(resid + ob1);
                *(float2*)(outF + ob0) = make_float2(v0 + br0 + r0.x, v1 + br0 + r0.y);
                *(float2*)(outF + ob1) = make_float2(v2 + br1 + r1.x, v3 + br1 + r1.y);
            } else {
                if (EPI == 1) { v0 += br0; v1 += br0; v2 += br1; v3 += br1; }
                *(__half2*)(outH + ob0) = __floats2half2_rn(v0, v1);
                *(__half2*)(outH + ob1) = __floats2half2_rn(v2, v3);
            }
        }
    }
}

// ---------------------------------------------------------------------------
// Softmax over rows of fp16 scores -> fp16 attn.
// ---------------------------------------------------------------------------
__global__ void softmax_kernel(const __half* __restrict__ src, __half* __restrict__ dst) {
    const size_t rbase = (size_t)blockIdx.x * NN_;
    uint2 rv = *(const uint2*)(src + rbase + threadIdx.x * 4);
    float2 a0 = __half22float2(*(const __half2*)&rv.x);
    float2 a1 = __half22float2(*(const __half2*)&rv.y);

    float m = fmaxf(fmaxf(a0.x, a0.y), fmaxf(a1.x, a1.y));
    #pragma unroll
    for (int o = 16; o; o >>= 1) m = fmaxf(m, __shfl_xor_sync(0xffffffffu, m, o));
    __shared__ float shm[8], shs[8];
    if ((threadIdx.x & 31) == 0) shm[threadIdx.x >> 5] = m;
    __syncthreads();
    float M = shm[0];
    #pragma unroll
    for (int i = 1; i < 8; i++) M = fmaxf(M, shm[i]);

    a0.x = __expf(a0.x - M); a0.y = __expf(a0.y - M);
    a1.x = __expf(a1.x - M); a1.y = __expf(a1.y - M);
    float s = a0.x + a0.y + a1.x + a1.y;
    #pragma unroll
    for (int o = 16; o; o >>= 1) s += __shfl_xor_sync(0xffffffffu, s, o);
    if ((threadIdx.x & 31) == 0) shs[threadIdx.x >> 5] = s;
    __syncthreads();
    float S = 0.f;
    #pragma unroll
    for (int i = 0; i < 8; i++) S += shs[i];
    const float r = 1.f / S;

    __half2 h0 = __floats2half2_rn(a0.x * r, a0.y * r);
    __half2 h1 = __floats2half2_rn(a1.x * r, a1.y * r);
    uint2 wv;
    wv.x = *(const uint32_t*)&h0;
    wv.y = *(const uint32_t*)&h1;
    *(uint2*)(dst + rbase + threadIdx.x * 4) = wv;
}

// ---------------------------------------------------------------------------
// Launch — 3 streams / 5 events. sV prologue (hides under GN):
// transpose x2 -> G -> wkbq = evPre. Then cvt(Wv,Wp) -> V = evV.
// Chains: beta -> z=xn.G -> scores(+beta_j) -> softmax -> AV -> proj.
// ---------------------------------------------------------------------------
static cudaStream_t sB = nullptr, sV = nullptr;
static cudaEvent_t evFork = nullptr, evGN = nullptr, evPre = nullptr,
                   evV = nullptr, evP1 = nullptr;

extern "C" void kernel_launch(void* const* d_in, const int* in_sizes, int n_in,
                              void* d_out, int out_size) {
    const float* x      = (const float*)d_in[0];
    const float* gamma  = (const float*)d_in[1];
    const float* beta   = (const float*)d_in[2];
    const float* w_qkv  = (const float*)d_in[3];
    const float* b_qkv  = (const float*)d_in[4];
    const float* w_proj = (const float*)d_in[5];
    const float* b_proj = (const float*)d_in[6];
    float* y = (float*)d_out;

    if (!sB) {
        cudaStreamCreateWithFlags(&sB, cudaStreamNonBlocking);
        cudaStreamCreateWithFlags(&sV, cudaStreamNonBlocking);
        cudaEventCreateWithFlags(&evFork, cudaEventDisableTiming);
        cudaEventCreateWithFlags(&evGN,   cudaEventDisableTiming);
        cudaEventCreateWithFlags(&evPre,  cudaEventDisableTiming);
        cudaEventCreateWithFlags(&evV,    cudaEventDisableTiming);
        cudaEventCreateWithFlags(&evP1,   cudaEventDisableTiming);
    }

    cudaFuncSetAttribute(gn_kernel,  cudaFuncAttributeMaxDynamicSharedMemorySize, 65536);
    cudaFuncSetAttribute(gemm_hh<1>, cudaFuncAttributeMaxDynamicSharedMemorySize, SMEM_BYTES);
    cudaFuncSetAttribute(gemm_hh<3>, cudaFuncAttributeMaxDynamicSharedMemorySize, SMEM_BYTES);
    cudaFuncSetAttribute(gemm_hh<4>, cudaFuncAttributeMaxDynamicSharedMemorySize, SMEM_BYTES);
    cudaFuncSetAttribute(gemm_hh<5>, cudaFuncAttributeMaxDynamicSharedMemorySize, SMEM_BYTES);

    __half *xn, *wv, *wp, *wqT, *wkT, *G, *z, *v, *s16, *a, *av;
    float *betaN;
    cudaGetSymbolAddress((void**)&xn,  g_xn);
    cudaGetSymbolAddress((void**)&wv,  g_wv);
    cudaGetSymbolAddress((void**)&wp,  g_wp);
    cudaGetSymbolAddress((void**)&wqT, g_wqT);
    cudaGetSymbolAddress((void**)&wkT, g_wkT);
    cudaGetSymbolAddress((void**)&G,   g_G);
    cudaGetSymbolAddress((void**)&z,   g_z);
    cudaGetSymbolAddress((void**)&v,   g_v);
    cudaGetSymbolAddress((void**)&s16, g_s);
    cudaGetSymbolAddress((void**)&a,   g_a);
    cudaGetSymbolAddress((void**)&av,  g_av);
    cudaGetSymbolAddress((void**)&betaN, g_betaN);

    const int HB = BB / 2;                           // 8 batches per chain
    const size_t bQ = (size_t)NN_ * NN_;
    const size_t bX = (size_t)NN_ * CC;
    const size_t bV = (size_t)CC * NN_;

    // fork
    cudaEventRecord(evFork, 0);
    cudaStreamWaitEvent(sV, evFork, 0);
    cudaStreamWaitEvent(sB, evFork, 0);

    // sV: minimal chain-gating prologue (hides under GN)
    transpose_cvt<<<dim3(16, 16), 256, 0, sV>>>(w_qkv, wqT);
    transpose_cvt<<<dim3(16, 16), 256, 0, sV>>>(w_qkv + (size_t)CC * CC, wkT);
    gemm_hh<3><<<dim3(4, 4, 1), 256, SMEM_BYTES, sV>>>(
        wqT, 0, CC,
        wkT, 0, CC, CC,
        G, nullptr, 0, CC, nullptr, nullptr);          // G = Wq^T Wk
    wkbq_kernel<<<CC / 8, 256, 0, sV>>>(wkT, b_qkv);
    cudaEventRecord(evPre, sV);

    // main: GroupNorm (all batches)
    gn_kernel<<<BB * 32, 256, 65536>>>(x, gamma, beta);
    cudaEventRecord(evGN, 0);

    // sV: converts needed only by V/proj, then V GEMM
    cvt_kernel<<<(CC * CC + 255) / 256, 256, 0, sV>>>(w_qkv + (size_t)2 * CC * CC, wv, CC * CC);
    cvt_kernel<<<(CC * CC + 255) / 256, 256, 0, sV>>>(w_proj, wp, CC * CC);
    cudaStreamWaitEvent(sV, evGN, 0);
    gemm_hh<1><<<dim3(8, 4, BB), 256, SMEM_BYTES, sV>>>(
        wv, 0, CC,
        xn, bX, CC, CC,
        v, nullptr, bV, NN_, b_qkv + 2 * CC, nullptr);
    cudaEventRecord(evV, sV);

    // ---- two chains (8 batches each), interleaved stage-by-stage ----
    cudaStreamWaitEvent(0, evPre, 0);
    cudaStreamWaitEvent(sB, evPre, 0);
    cudaStreamWaitEvent(sB, evGN, 0);

    cudaStream_t st[2] = { 0, sB };
    __half* z_h[2]; __half* s_h[2]; __half* a_h[2]; __half* xn_h[2];
    __half* v_h[2]; __half* av_h[2]; float* y_h[2]; const float* x_h[2];
    float* be_h[2];
    for (int h = 0; h < 2; h++) {
        const int bo = h * HB;
        z_h[h]   = z   + (size_t)bo * bX;
        s_h[h]   = s16 + (size_t)bo * bQ;
        a_h[h]   = a   + (size_t)bo * bQ;
        xn_h[h]  = xn  + (size_t)bo * bX;
        v_h[h]   = v   + (size_t)bo * bV;
        av_h[h]  = av  + (size_t)bo * bX;
        y_h[h]   = y   + (size_t)bo * bV;
        x_h[h]   = x   + (size_t)bo * bV;
        be_h[h]  = betaN + (size_t)bo * NN_;
    }

    // beta_j (exact bias correction; alpha/kappa cancel in softmax)
    for (int h = 0; h < 2; h++)
        beta_kernel<<<HB * NN_ / 8, 256, 0, st[h]>>>(xn_h[h], be_h[h]);

    // z = xn . G  (replaces both q and k projections)
    for (int h = 0; h < 2; h++)
        gemm_hh<3><<<dim3(4, 8, HB), 256, SMEM_BYTES, st[h]>>>(
            xn_h[h], bX, CC,
            G, 0, CC, CC,
            z_h[h], nullptr, bX, CC, nullptr, nullptr);

    // scores: S[i][j] = (xn_i . z_j + beta_j) * SCALE
    for (int h = 0; h < 2; h++)
        gemm_hh<5><<<dim3(8, 8, HB), 256, SMEM_BYTES, st[h]>>>(
            xn_h[h], bX, CC,
            z_h[h], bX, CC, CC,
            s_h[h], nullptr, bQ, NN_, be_h[h], nullptr);

    // softmax
    for (int h = 0; h < 2; h++)
        softmax_kernel<<<HB * NN_, 256, 0, st[h]>>>(s_h[h], a_h[h]);

    // AV
    for (int h = 0; h < 2; h++) {
        cudaStreamWaitEvent(st[h], evV, 0);
        gemm_hh<3><<<dim3(4, 8, HB), 256, SMEM_BYTES, st[h]>>>(
            a_h[h], bQ, NN_,
            v_h[h], bV, NN_, NN_,
            av_h[h], nullptr, bX, CC, nullptr, nullptr);
    }

    // proj + residual
    for (int h = 0; h < 2; h++)
        gemm_hh<4><<<dim3(8, 4, HB), 256, SMEM_BYTES, st[h]>>>(
            wp, 0, CC,
            av_h[h], bX, CC, CC,
            nullptr, y_h[h], bV, NN_, b_proj, x_h[h]);

    // join sB back into stream 0
    cudaEventRecord(evP1, sB);
    cudaStreamWaitEvent(0, evP1, 0);
}